// round 11
// baseline (speedup 1.0000x reference)
#include <cuda_runtime.h>
#include <cuda_bf16.h>
#include <cstdint>

#define NB  8
#define EHD 768
#define TD  512
#define PHD 320
#define UD  128
#define JHD 320
#define NC  34
#define WST 36            // w table stride [j][36]
#define KT  32            // proj k-tile

typedef unsigned long long ull;

// Scratch (allocation-free rule: device globals)
__device__ float g_e[NB * TD * JHD];    // (B, T, JH)
__device__ float g_p[NB * UD * JHD];    // (B, U, JH)
__device__ float g_wt[JHD * WST];       // W_out transposed [j][c], padded

// ---------------- f32x2 helpers ----------------
static __device__ __forceinline__ ull pack2(float x, float y) {
    ull r;
    asm("mov.b64 %0, {%1, %2};" : "=l"(r) : "f"(x), "f"(y));
    return r;
}
static __device__ __forceinline__ void unpack2(ull v, float& x, float& y) {
    asm("mov.b64 {%0, %1}, %2;" : "=f"(x), "=f"(y) : "l"(v));
}
static __device__ __forceinline__ void ffma2(ull& acc, ull a, ull b) {
    asm("fma.rn.f32x2 %0, %1, %2, %0;" : "+l"(acc) : "l"(a), "l"(b));
}

// ---------------- merged projection GEMM v3 + prep branch (unchanged) ----------------
#define WSTR 132   // 528B rows

__global__ __launch_bounds__(128) void proj_all_kernel(
    const float* __restrict__ enc, const float* __restrict__ W_enc,
    const float* __restrict__ b_enc,
    const float* __restrict__ dec, const float* __restrict__ W_pred,
    const float* __restrict__ b_pred,
    const float* __restrict__ W_out,
    float* __restrict__ e_out, float* __restrict__ p_out)
{
    if (blockIdx.x == 20) {
        int base = (blockIdx.z * 5 + blockIdx.y) * 128 + threadIdx.x;
        for (int idx = base; idx < JHD * WST; idx += 5 * NB * 128) {
            int j = idx / WST, c = idx - j * WST;
            g_wt[idx] = (c < NC) ? W_out[c * JHD + j] : 0.f;
        }
        return;
    }

    __shared__ float Xs[2][KT][36];
    __shared__ float Ws[2][KT][WSTR];

    const float* X; const float* W; const float* bias; float* out;
    int H, L, l0;
    if (blockIdx.x < 16) {
        X = enc; W = W_enc; bias = b_enc; out = e_out;
        H = EHD; L = TD; l0 = blockIdx.x * 32;
    } else {
        X = dec; W = W_pred; bias = b_pred; out = p_out;
        H = PHD; L = UD; l0 = (blockIdx.x - 16) * 32;
    }
    const int b  = blockIdx.z;
    const int j0 = blockIdx.y * 64;
    const int tid = threadIdx.x;
    const int tl = tid & 7;
    const int tj = tid >> 3;

    ull acc[4][2];
#pragma unroll
    for (int m = 0; m < 4; m++) { acc[m][0] = 0ull; acc[m][1] = 0ull; }

    const int kkL = tid >> 2, vL = tid & 3;
    const int jW = tid >> 1, kq2 = tid & 1;

    const float* Xg = X + ((size_t)b * H + kkL) * L + l0;
    const float* Wg = W + (size_t)(j0 + jW) * H;
    const int NT = H / KT;

    float4 xr[2], wr[4];
#pragma unroll
    for (int i = 0; i < 2; i++)
        xr[i] = *(const float4*)(Xg + (vL + 4 * i) * 4);
#pragma unroll
    for (int i = 0; i < 4; i++)
        wr[i] = *(const float4*)(Wg + (kq2 + 2 * i) * 4);

#pragma unroll 1
    for (int tile = 0; tile < NT; tile++) {
        const int buf = tile & 1;
#pragma unroll
        for (int i = 0; i < 2; i++)
            *(float4*)&Xs[buf][kkL][(vL + 4 * i) * 4] = xr[i];
#pragma unroll
        for (int i = 0; i < 4; i++) {
            const int kq = kq2 + 2 * i;
            *(float2*)&Ws[buf][kq * 4 + 0][jW * 2] = make_float2(wr[i].x, wr[i].x);
            *(float2*)&Ws[buf][kq * 4 + 1][jW * 2] = make_float2(wr[i].y, wr[i].y);
            *(float2*)&Ws[buf][kq * 4 + 2][jW * 2] = make_float2(wr[i].z, wr[i].z);
            *(float2*)&Ws[buf][kq * 4 + 3][jW * 2] = make_float2(wr[i].w, wr[i].w);
        }
        __syncthreads();
        if (tile + 1 < NT) {
            const int h0 = (tile + 1) * KT;
#pragma unroll
            for (int i = 0; i < 2; i++)
                xr[i] = *(const float4*)(Xg + (size_t)h0 * L + (vL + 4 * i) * 4);
#pragma unroll
            for (int i = 0; i < 4; i++)
                wr[i] = *(const float4*)(Wg + h0 + (kq2 + 2 * i) * 4);
        }
#pragma unroll
        for (int kk = 0; kk < KT; kk++) {
            ulonglong2 ap = *(const ulonglong2*)&Xs[buf][kk][tl * 4];
            ulonglong2 wa = *(const ulonglong2*)&Ws[buf][kk][tj * 8];
            ulonglong2 wb = *(const ulonglong2*)&Ws[buf][kk][tj * 8 + 4];
            ffma2(acc[0][0], wa.x, ap.x); ffma2(acc[0][1], wa.x, ap.y);
            ffma2(acc[1][0], wa.y, ap.x); ffma2(acc[1][1], wa.y, ap.y);
            ffma2(acc[2][0], wb.x, ap.x); ffma2(acc[2][1], wb.x, ap.y);
            ffma2(acc[3][0], wb.y, ap.x); ffma2(acc[3][1], wb.y, ap.y);
        }
        if (tile + 1 < NT) __syncthreads();
    }

    float4 bi = *(const float4*)(bias + j0 + tj * 4);
#pragma unroll
    for (int pp = 0; pp < 2; pp++) {
        float a0x, a0y, a1x, a1y, a2x, a2y, a3x, a3y;
        unpack2(acc[0][pp], a0x, a0y);
        unpack2(acc[1][pp], a1x, a1y);
        unpack2(acc[2][pp], a2x, a2y);
        unpack2(acc[3][pp], a3x, a3y);
        const int l = l0 + tl * 4 + pp * 2;
        float4 o0 = make_float4(a0x + bi.x, a1x + bi.y, a2x + bi.z, a3x + bi.w);
        float4 o1 = make_float4(a0y + bi.x, a1y + bi.y, a2y + bi.z, a3y + bi.w);
        *(float4*)(out + ((size_t)b * L + l    ) * JHD + j0 + tj * 4) = o0;
        *(float4*)(out + ((size_t)b * L + l + 1) * JHD + j0 + tj * 4) = o1;
    }
}

// ---------------- joint v4.1: 2t x 2u x 18-class split (cg*18, LDS.64 w-reads) ----------------
#define EST 18
#define PST 34
#define JS_E (JHD * EST)              // 5760 floats
#define JS_P (JHD * PST)              // 10880 floats
#define JS_W (JHD * WST + 2)          // 11522 floats (+2 pad)
#define JS_TOTAL ((JS_E + JS_P + JS_W) * 4)

__global__ __launch_bounds__(256, 2) void joint_kernel(
    const float* __restrict__ e, const float* __restrict__ p,
    const float* __restrict__ wt, const float* __restrict__ bo,
    float* __restrict__ out)
{
    extern __shared__ float sm[];
    float* e_s = sm;                     // [j][t] stride 18 (t-pair LDS.64, broadcast)
    float* p_s = sm + JS_E;              // [j][u] stride 34 (u-pair LDS.64)
    float* w_s = sm + JS_E + JS_P;       // [j][c] stride 36 (+2 pad)
    __shared__ float b_s[NC];

    const int tid  = threadIdx.x;
    const int wid  = tid >> 5;           // t-pair: t = 2*wid, 2*wid+1
    const int lane = tid & 31;
    const int ul   = lane & 15;          // u-pair: u = 2*ul, 2*ul+1
    const int cg   = lane >> 4;          // class group: 0 -> 0..17, 1 -> 18..35(pad)
    const int b    = blockIdx.z;
    const int tg   = blockIdx.y * 16;
    const int ublk = blockIdx.x;         // 0..3

    // p transposed, stride 34
    {
        const float* pb = p + ((size_t)b * UD + ublk * 32) * JHD;
        for (int idx = tid; idx < 32 * JHD; idx += 256) {
            int u = idx / JHD, j = idx - u * JHD;
            p_s[j * PST + u] = pb[idx];
        }
    }
    // e transposed, stride 18 (one-time store conflicts, fine)
    {
        const float* eb = e + ((size_t)b * TD + tg) * JHD;
        for (int idx = tid; idx < 16 * JHD; idx += 256) {
            int t = idx / JHD, j = idx - t * JHD;
            e_s[j * EST + t] = eb[idx];
        }
    }
    // w straight copy + tail pad
    for (int idx = tid; idx < JHD * WST; idx += 256) w_s[idx] = wt[idx];
    if (tid < 2) w_s[JHD * WST + tid] = 0.f;
    if (tid < NC) b_s[tid] = bo[tid];
    __syncthreads();

    // bias init (class pairs for this cg; pad classes -> 0)
    ull acc[4][9];
    {
#pragma unroll
        for (int q = 0; q < 9; q++) {
            int c = cg * 18 + 2 * q;
            float bx_ = (c     < NC) ? b_s[c]     : 0.f;
            float by_ = (c + 1 < NC) ? b_s[c + 1] : 0.f;
            ull bp = pack2(bx_, by_);
            acc[0][q] = bp; acc[1][q] = bp; acc[2][q] = bp; acc[3][q] = bp;
        }
    }

    const float* eb2 = e_s + 2 * wid;
    const float* pb2 = p_s + 2 * ul;
    const float* wb  = w_s + cg * 18;    // FIXED: matches bias/store indexing

    float2 ev = *(const float2*)(eb2);
    float2 pv = *(const float2*)(pb2);

#pragma unroll 1
    for (int j = 0; j < JHD; j++) {
        // prefetch next (final iter overreads into adjacent smem regions, unused)
        float2 evn = *(const float2*)(eb2 + (j + 1) * EST);
        float2 pvn = *(const float2*)(pb2 + (j + 1) * PST);

        // 9 x LDS.64 (8B-aligned for both cg halves; two broadcast addrs/instr,
        // disjoint banks -> 1 wavefront each)
        const ull* wj = (const ull*)(wb + j * WST);
        ull w0 = wj[0], w1 = wj[1], w2 = wj[2], w3 = wj[3], w4 = wj[4];
        ull w5 = wj[5], w6 = wj[6], w7 = wj[7], w8 = wj[8];

        float h00 = fmaxf(ev.x + pv.x, 0.f);
        float h01 = fmaxf(ev.x + pv.y, 0.f);
        float h10 = fmaxf(ev.y + pv.x, 0.f);
        float h11 = fmaxf(ev.y + pv.y, 0.f);
        ull hp0 = pack2(h00, h00);
        ull hp1 = pack2(h01, h01);
        ull hp2 = pack2(h10, h10);
        ull hp3 = pack2(h11, h11);

#pragma unroll
        for (int r = 0; r < 4; r++) {
            ull hr = (r == 0) ? hp0 : (r == 1) ? hp1 : (r == 2) ? hp2 : hp3;
            ffma2(acc[r][0], hr, w0);
            ffma2(acc[r][1], hr, w1);
            ffma2(acc[r][2], hr, w2);
            ffma2(acc[r][3], hr, w3);
            ffma2(acc[r][4], hr, w4);
            ffma2(acc[r][5], hr, w5);
            ffma2(acc[r][6], hr, w6);
            ffma2(acc[r][7], hr, w7);
            ffma2(acc[r][8], hr, w8);
        }
        ev = evn; pv = pvn;
    }

    // ---- epilogue: split log_softmax via shfl, store own classes ----
#pragma unroll 1
    for (int r = 0; r < 4; r++) {
        const int ti = r >> 1, ui = r & 1;
        float lg[18];
#pragma unroll
        for (int q = 0; q < 9; q++) unpack2(acc[r][q], lg[2 * q], lg[2 * q + 1]);

        float s = 0.f;
#pragma unroll
        for (int c = 0; c < 16; c++) s += __expf(lg[c]);
        if (cg == 0) s += __expf(lg[16]) + __expf(lg[17]);
        s += __shfl_xor_sync(0xFFFFFFFFu, s, 16);
        const float lse = __logf(s);

        const int t = tg + 2 * wid + ti;
        const int u = ublk * 32 + 2 * ul + ui;
        float* op = out + (((size_t)b * TD + t) * UD + u) * NC + cg * 18;
#pragma unroll
        for (int q = 0; q < 8; q++)
            *(float2*)(op + 2 * q) = make_float2(lg[2 * q] - lse, lg[2 * q + 1] - lse);
        if (cg == 0)
            *(float2*)(op + 16) = make_float2(lg[16] - lse, lg[17] - lse);
    }
}

// ---------------- launch ----------------
extern "C" void kernel_launch(void* const* d_in, const int* in_sizes, int n_in,
                              void* d_out, int out_size)
{
    const float* enc    = (const float*)d_in[0];
    const float* dec    = (const float*)d_in[1];
    const float* W_enc  = (const float*)d_in[2];
    const float* b_enc  = (const float*)d_in[3];
    const float* W_pred = (const float*)d_in[4];
    const float* b_pred = (const float*)d_in[5];
    const float* W_out  = (const float*)d_in[6];
    const float* b_out  = (const float*)d_in[7];
    float* out = (float*)d_out;

    float *e_buf = nullptr, *p_buf = nullptr, *wt = nullptr;
    cudaGetSymbolAddress((void**)&e_buf, g_e);
    cudaGetSymbolAddress((void**)&p_buf, g_p);
    cudaGetSymbolAddress((void**)&wt, g_wt);

    cudaFuncSetAttribute(joint_kernel,
                         cudaFuncAttributeMaxDynamicSharedMemorySize, JS_TOTAL);

    proj_all_kernel<<<dim3(21, 5, NB), 128>>>(enc, W_enc, b_enc,
                                              dec, W_pred, b_pred, W_out,
                                              e_buf, p_buf);
    joint_kernel<<<dim3(UD / 32, TD / 16, NB), 256, JS_TOTAL>>>(
        e_buf, p_buf, wt, b_out, out);
}